// round 6
// baseline (speedup 1.0000x reference)
#include <cuda_runtime.h>
#include <cuda_bf16.h>

#define N_NODES   80000
#define NODES_PB  10000
#define NBATCH    8
#define NEDGES    2560000
#define IN_DIM    128
#define H1        32
#define H2        64

#define SCAN_B    1024
#define NBLK_SCAN ((N_NODES + SCAN_B - 1) / SCAN_B)   // 79

// ---- scratch (__device__ globals; no allocation allowed) ----
__device__ float g_dinv[N_NODES];
__device__ int   g_cnt[N_NODES];
__device__ int   g_rowstart[N_NODES + 1];
__device__ int   g_cursor[N_NODES];
__device__ int   g_bsum[NBLK_SCAN];
__device__ int   g_boff[NBLK_SCAN];
__device__ int   g_esrc[NEDGES];
__device__ float g_ew[NEDGES];

__device__ float g_h1t[N_NODES * H1];    // x@W1
__device__ float g_h1o[N_NODES * H1];    // relu(agg1+b1)
__device__ float g_h2t[N_NODES * H2];    // h1o@W2
__device__ float g_h2o[N_NODES * H2];    // relu(agg2+b2)

// ---------------------------------------------------------------------------
// CSR build
// ---------------------------------------------------------------------------
__global__ void k_cnt_init() {
    int i = blockIdx.x * blockDim.x + threadIdx.x;
    if (i < N_NODES) g_cnt[i] = 0;
}

__global__ void k_deg_count(const int* __restrict__ ei) {
    int e = blockIdx.x * blockDim.x + threadIdx.x;
    if (e < NEDGES) {
        int d = ei[NEDGES + e];
        atomicAdd(&g_cnt[d], 1);
    }
}

// per-block sums of counts
__global__ void k_scan_a() {
    __shared__ int sh[SCAN_B / 32];
    int i = blockIdx.x * SCAN_B + threadIdx.x;
    int v = (i < N_NODES) ? g_cnt[i] : 0;
    #pragma unroll
    for (int o = 16; o > 0; o >>= 1) v += __shfl_down_sync(0xFFFFFFFFu, v, o);
    if ((threadIdx.x & 31) == 0) sh[threadIdx.x >> 5] = v;
    __syncthreads();
    if (threadIdx.x < SCAN_B / 32) {
        int t = sh[threadIdx.x];
        #pragma unroll
        for (int o = SCAN_B / 64; o > 0; o >>= 1) t += __shfl_down_sync(0xFFFFFFFFu, t, o);
        if (threadIdx.x == 0) g_bsum[blockIdx.x] = t;
    }
}

// tiny serial scan of block sums
__global__ void k_scan_b() {
    if (threadIdx.x == 0) {
        int run = 0;
        for (int b = 0; b < NBLK_SCAN; b++) { g_boff[b] = run; run += g_bsum[b]; }
        g_rowstart[N_NODES] = run;   // == NEDGES
    }
}

// per-block exclusive scan + finalize dinv
__global__ void k_scan_c() {
    __shared__ int sh[SCAN_B];
    int tid = threadIdx.x;
    int i = blockIdx.x * SCAN_B + tid;
    int v = (i < N_NODES) ? g_cnt[i] : 0;
    sh[tid] = v;
    __syncthreads();
    #pragma unroll
    for (int off = 1; off < SCAN_B; off <<= 1) {
        int t = (tid >= off) ? sh[tid - off] : 0;
        __syncthreads();
        sh[tid] += t;
        __syncthreads();
    }
    if (i < N_NODES) {
        int excl = sh[tid] - v + g_boff[blockIdx.x];
        g_rowstart[i] = excl;
        g_cursor[i]   = excl;
        g_dinv[i]     = rsqrtf((float)(v + 1));   // +1 self-loop
    }
}

__global__ void k_place(const int* __restrict__ ei) {
    int e = blockIdx.x * blockDim.x + threadIdx.x;
    if (e >= NEDGES) return;
    int s = ei[e];
    int d = ei[NEDGES + e];
    int slot = atomicAdd(&g_cursor[d], 1);
    g_esrc[slot] = s;
    g_ew[slot]   = g_dinv[s] * g_dinv[d];
}

// ---------------------------------------------------------------------------
// GEMM1: g_h1t = x @ W1   (80000x128 @ 128x32)
// ---------------------------------------------------------------------------
__global__ void k_gemm1(const float* __restrict__ x, const float* __restrict__ W1) {
    __shared__ float Ws[IN_DIM * H1];
    __shared__ float xs[32][IN_DIM];
    int row0 = blockIdx.x * 32;

    for (int i = threadIdx.x; i < IN_DIM * H1; i += 256) Ws[i] = W1[i];
    for (int i = threadIdx.x; i < 32 * IN_DIM; i += 256) {
        int r = i >> 7, k = i & 127;
        xs[r][k] = x[(size_t)(row0 + r) * IN_DIM + k];
    }
    __syncthreads();

    int col  = threadIdx.x & 31;
    int rsub = threadIdx.x >> 5;
    for (int r = rsub; r < 32; r += 8) {
        float acc = 0.f;
        #pragma unroll 16
        for (int k = 0; k < IN_DIM; k++) acc += xs[r][k] * Ws[k * H1 + col];
        g_h1t[(size_t)(row0 + r) * H1 + col] = acc;
    }
}

// ---------------------------------------------------------------------------
// gather layer 1: warp per node, lane = feature col. Fuses self-loop+bias+relu.
// ---------------------------------------------------------------------------
__global__ void k_gather1(const float* __restrict__ b1) {
    int wid  = (blockIdx.x * blockDim.x + threadIdx.x) >> 5;
    int lane = threadIdx.x & 31;
    if (wid >= N_NODES) return;
    int beg = g_rowstart[wid], end = g_rowstart[wid + 1];
    float dn  = g_dinv[wid];
    float acc = g_h1t[(size_t)wid * H1 + lane] * dn * dn;
    for (int e = beg; e < end; e++) {
        int   s = g_esrc[e];
        float w = g_ew[e];
        acc += g_h1t[(size_t)s * H1 + lane] * w;
    }
    g_h1o[(size_t)wid * H1 + lane] = fmaxf(acc + b1[lane], 0.f);
}

// ---------------------------------------------------------------------------
// GEMM2: g_h2t = h1o @ W2   (80000x32 @ 32x64)
// ---------------------------------------------------------------------------
__global__ void k_gemm2(const float* __restrict__ W2) {
    __shared__ float Ws[H1 * H2];
    __shared__ float xs[64][H1];
    int row0 = blockIdx.x * 64;

    for (int i = threadIdx.x; i < H1 * H2; i += 256) Ws[i] = W2[i];
    for (int i = threadIdx.x; i < 64 * H1; i += 256) {
        int r = i >> 5, k = i & 31;
        xs[r][k] = g_h1o[(size_t)(row0 + r) * H1 + k];
    }
    __syncthreads();

    int col  = threadIdx.x & 63;
    int rsub = threadIdx.x >> 6;
    for (int r = rsub; r < 64; r += 4) {
        float acc = 0.f;
        #pragma unroll
        for (int k = 0; k < H1; k++) acc += xs[r][k] * Ws[k * H2 + col];
        g_h2t[(size_t)(row0 + r) * H2 + col] = acc;
    }
}

// ---------------------------------------------------------------------------
// gather layer 2: warp per node, 2 feature cols per lane.
// ---------------------------------------------------------------------------
__global__ void k_gather2(const float* __restrict__ b2) {
    int wid  = (blockIdx.x * blockDim.x + threadIdx.x) >> 5;
    int lane = threadIdx.x & 31;
    if (wid >= N_NODES) return;
    int beg = g_rowstart[wid], end = g_rowstart[wid + 1];
    float dn = g_dinv[wid];
    const size_t base = (size_t)wid * H2;
    float acc0 = g_h2t[base + lane]      * dn * dn;
    float acc1 = g_h2t[base + lane + 32] * dn * dn;
    for (int e = beg; e < end; e++) {
        int    s  = g_esrc[e];
        float  w  = g_ew[e];
        size_t sb = (size_t)s * H2;
        acc0 += g_h2t[sb + lane]      * w;
        acc1 += g_h2t[sb + lane + 32] * w;
    }
    g_h2o[base + lane]      = fmaxf(acc0 + b2[lane],      0.f);
    g_h2o[base + lane + 32] = fmaxf(acc1 + b2[lane + 32], 0.f);
}

// ---------------------------------------------------------------------------
// readout
// ---------------------------------------------------------------------------
__global__ void k_out_init(float* __restrict__ out, const float* __restrict__ bout) {
    int b = threadIdx.x;
    if (b < NBATCH) out[b] = bout[0];
}

__global__ void k_out_reduce(const float* __restrict__ Wout, float* __restrict__ out) {
    const int LEN = NODES_PB * H2;   // 640000
    int b = blockIdx.y;
    const float* h = g_h2o + (size_t)b * LEN;
    float s = 0.f;
    for (int j = blockIdx.x * blockDim.x + threadIdx.x; j < LEN; j += gridDim.x * blockDim.x)
        s += h[j] * Wout[j];
    #pragma unroll
    for (int o = 16; o > 0; o >>= 1) s += __shfl_down_sync(0xFFFFFFFFu, s, o);
    __shared__ float ws[8];
    if ((threadIdx.x & 31) == 0) ws[threadIdx.x >> 5] = s;
    __syncthreads();
    if (threadIdx.x < 8) {
        float t = ws[threadIdx.x];
        #pragma unroll
        for (int o = 4; o > 0; o >>= 1) t += __shfl_down_sync(0xFFu, t, o);
        if (threadIdx.x == 0) atomicAdd(&out[b], t);
    }
}

// ---------------------------------------------------------------------------
extern "C" void kernel_launch(void* const* d_in, const int* in_sizes, int n_in,
                              void* d_out, int out_size) {
    const float* x    = (const float*)d_in[0];
    const int*   ei   = (const int*)d_in[1];     // int32! (JAX demotes int64 without x64)
    const float* W1   = (const float*)d_in[2];
    const float* b1   = (const float*)d_in[3];
    const float* W2   = (const float*)d_in[4];
    const float* b2   = (const float*)d_in[5];
    const float* Wout = (const float*)d_in[6];
    const float* bout = (const float*)d_in[7];
    float*       out  = (float*)d_out;

    const int T = 256;
    const int nodeBlk = (N_NODES + T - 1) / T;
    const int edgeBlk = (NEDGES + T - 1) / T;

    // CSR build
    k_cnt_init<<<nodeBlk, T>>>();
    k_deg_count<<<edgeBlk, T>>>(ei);
    k_scan_a<<<NBLK_SCAN, SCAN_B>>>();
    k_scan_b<<<1, 32>>>();
    k_scan_c<<<NBLK_SCAN, SCAN_B>>>();
    k_place<<<edgeBlk, T>>>(ei);

    // layer 1
    k_gemm1<<<N_NODES / 32, T>>>(x, W1);
    k_gather1<<<(N_NODES * 32 + T - 1) / T, T>>>(b1);

    // layer 2
    k_gemm2<<<N_NODES / 64, T>>>(W2);
    k_gather2<<<(N_NODES * 32 + T - 1) / T, T>>>(b2);

    // readout
    k_out_init<<<1, 32>>>(out, bout);
    dim3 og(40, NBATCH);
    k_out_reduce<<<og, T>>>(Wout, out);
}

// round 7
// speedup vs baseline: 1.0334x; 1.0334x over previous
#include <cuda_runtime.h>
#include <cuda_bf16.h>

#define N_NODES   80000
#define NODES_PB  10000
#define NBATCH    8
#define NEDGES    2560000
#define IN_DIM    128
#define H1        32
#define H2        64

#define SCAN_B    1024
#define NBLK_SCAN ((N_NODES + SCAN_B - 1) / SCAN_B)   // 79

// ---- scratch (__device__ globals; no allocation allowed) ----
__device__ float g_dinv[N_NODES];
__device__ int   g_cnt[N_NODES];
__device__ int   g_rowstart[N_NODES + 1];
__device__ int   g_cursor[N_NODES];
__device__ int   g_bsum[NBLK_SCAN];
__device__ int2  g_edge[NEDGES];               // {src, weight-as-bits}

__device__ __align__(128) float g_h1t[N_NODES * H1];  // x@W1
__device__ __align__(128) float g_h1o[N_NODES * H1];  // relu(agg1+b1)
__device__ __align__(128) float g_a2 [N_NODES * H1];  // agg(h1o)  (32 cols!)
__device__ __align__(128) float g_h2o[N_NODES * H2];  // relu(a2@W2+b2)

// ---------------------------------------------------------------------------
// CSR build
// ---------------------------------------------------------------------------
__global__ void k_cnt_init() {
    int i = blockIdx.x * blockDim.x + threadIdx.x;
    if (i < N_NODES) g_cnt[i] = 0;
}

__global__ void k_deg_count(const int* __restrict__ ei) {
    int e = blockIdx.x * blockDim.x + threadIdx.x;
    if (e < NEDGES) atomicAdd(&g_cnt[ei[NEDGES + e]], 1);
}

// per-block sums of counts
__global__ void k_scan_a() {
    __shared__ int sh[SCAN_B / 32];
    int i = blockIdx.x * SCAN_B + threadIdx.x;
    int v = (i < N_NODES) ? g_cnt[i] : 0;
    #pragma unroll
    for (int o = 16; o > 0; o >>= 1) v += __shfl_down_sync(0xFFFFFFFFu, v, o);
    if ((threadIdx.x & 31) == 0) sh[threadIdx.x >> 5] = v;
    __syncthreads();
    if (threadIdx.x < SCAN_B / 32) {
        int t = sh[threadIdx.x];
        #pragma unroll
        for (int o = SCAN_B / 64; o > 0; o >>= 1) t += __shfl_down_sync(0xFFFFFFFFu, t, o);
        if (threadIdx.x == 0) g_bsum[blockIdx.x] = t;
    }
    if (blockIdx.x == 0 && threadIdx.x == 0) g_rowstart[N_NODES] = NEDGES;
}

// per-block exclusive scan; each block re-reduces its prefix of g_bsum (cheap, parallel)
__global__ void k_scan_c() {
    __shared__ int sh[SCAN_B];
    __shared__ int s_off;
    int tid = threadIdx.x;

    if (tid < 32) {
        int v = 0;
        for (int b = tid; b < blockIdx.x; b += 32) v += g_bsum[b];
        #pragma unroll
        for (int o = 16; o > 0; o >>= 1) v += __shfl_down_sync(0xFFFFFFFFu, v, o);
        if (tid == 0) s_off = v;
    }

    int i = blockIdx.x * SCAN_B + tid;
    int v = (i < N_NODES) ? g_cnt[i] : 0;
    sh[tid] = v;
    __syncthreads();
    #pragma unroll
    for (int off = 1; off < SCAN_B; off <<= 1) {
        int t = (tid >= off) ? sh[tid - off] : 0;
        __syncthreads();
        sh[tid] += t;
        __syncthreads();
    }
    if (i < N_NODES) {
        int excl = sh[tid] - v + s_off;
        g_rowstart[i] = excl;
        g_cursor[i]   = excl;
        g_dinv[i]     = rsqrtf((float)(v + 1));   // +1 self-loop
    }
}

__global__ void k_place(const int* __restrict__ ei) {
    int e = blockIdx.x * blockDim.x + threadIdx.x;
    if (e >= NEDGES) return;
    int s = ei[e];
    int d = ei[NEDGES + e];
    int slot = atomicAdd(&g_cursor[d], 1);
    g_edge[slot] = make_int2(s, __float_as_int(g_dinv[s] * g_dinv[d]));
}

// ---------------------------------------------------------------------------
// GEMM1: g_h1t = x @ W1   (80000x128 @ 128x32)
// ---------------------------------------------------------------------------
__global__ void k_gemm1(const float* __restrict__ x, const float* __restrict__ W1) {
    __shared__ float Ws[IN_DIM * H1];
    __shared__ float xs[32][IN_DIM];
    int row0 = blockIdx.x * 32;

    for (int i = threadIdx.x; i < IN_DIM * H1; i += 256) Ws[i] = W1[i];
    for (int i = threadIdx.x; i < 32 * IN_DIM; i += 256) {
        int r = i >> 7, k = i & 127;
        xs[r][k] = x[(size_t)(row0 + r) * IN_DIM + k];
    }
    __syncthreads();

    int col  = threadIdx.x & 31;
    int rsub = threadIdx.x >> 5;
    for (int r = rsub; r < 32; r += 8) {
        float acc = 0.f;
        #pragma unroll 16
        for (int k = 0; k < IN_DIM; k++) acc += xs[r][k] * Ws[k * H1 + col];
        g_h1t[(size_t)(row0 + r) * H1 + col] = acc;
    }
}

// ---------------------------------------------------------------------------
// gather1: warp per node over g_h1t (32 cols). Fuses self-loop + bias + relu.
// ---------------------------------------------------------------------------
__global__ void k_gather1(const float* __restrict__ b1) {
    int node = (blockIdx.x * blockDim.x + threadIdx.x) >> 5;
    int lane = threadIdx.x & 31;
    if (node >= N_NODES) return;
    int beg = g_rowstart[node], end = g_rowstart[node + 1];
    float dn  = g_dinv[node];
    float acc = g_h1t[(size_t)node * H1 + lane] * dn * dn;

    int e = beg;
    for (; e + 4 <= end; e += 4) {
        int2 e0 = g_edge[e], e1 = g_edge[e + 1], e2 = g_edge[e + 2], e3 = g_edge[e + 3];
        float v0 = g_h1t[(size_t)e0.x * H1 + lane];
        float v1 = g_h1t[(size_t)e1.x * H1 + lane];
        float v2 = g_h1t[(size_t)e2.x * H1 + lane];
        float v3 = g_h1t[(size_t)e3.x * H1 + lane];
        acc += v0 * __int_as_float(e0.y);
        acc += v1 * __int_as_float(e1.y);
        acc += v2 * __int_as_float(e2.y);
        acc += v3 * __int_as_float(e3.y);
    }
    for (; e < end; e++) {
        int2 ev = g_edge[e];
        acc += g_h1t[(size_t)ev.x * H1 + lane] * __int_as_float(ev.y);
    }
    g_h1o[(size_t)node * H1 + lane] = fmaxf(acc + b1[lane], 0.f);
}

// ---------------------------------------------------------------------------
// gather2: warp per node over g_h1o (32 cols). agg only (no bias/relu):
//   a2 = agg(h1o)   [then a2 @ W2 == agg(h1o @ W2) by linearity]
// ---------------------------------------------------------------------------
__global__ void k_gather2() {
    int node = (blockIdx.x * blockDim.x + threadIdx.x) >> 5;
    int lane = threadIdx.x & 31;
    if (node >= N_NODES) return;
    int beg = g_rowstart[node], end = g_rowstart[node + 1];
    float dn  = g_dinv[node];
    float acc = g_h1o[(size_t)node * H1 + lane] * dn * dn;

    int e = beg;
    for (; e + 4 <= end; e += 4) {
        int2 e0 = g_edge[e], e1 = g_edge[e + 1], e2 = g_edge[e + 2], e3 = g_edge[e + 3];
        float v0 = g_h1o[(size_t)e0.x * H1 + lane];
        float v1 = g_h1o[(size_t)e1.x * H1 + lane];
        float v2 = g_h1o[(size_t)e2.x * H1 + lane];
        float v3 = g_h1o[(size_t)e3.x * H1 + lane];
        acc += v0 * __int_as_float(e0.y);
        acc += v1 * __int_as_float(e1.y);
        acc += v2 * __int_as_float(e2.y);
        acc += v3 * __int_as_float(e3.y);
    }
    for (; e < end; e++) {
        int2 ev = g_edge[e];
        acc += g_h1o[(size_t)ev.x * H1 + lane] * __int_as_float(ev.y);
    }
    g_a2[(size_t)node * H1 + lane] = acc;
}

// ---------------------------------------------------------------------------
// GEMM2: g_h2o = relu(a2 @ W2 + b2)   (80000x32 @ 32x64, fused epilogue)
// ---------------------------------------------------------------------------
__global__ void k_gemm2(const float* __restrict__ W2, const float* __restrict__ b2) {
    __shared__ float Ws[H1 * H2];
    __shared__ float xs[64][H1];
    int row0 = blockIdx.x * 64;

    for (int i = threadIdx.x; i < H1 * H2; i += 256) Ws[i] = W2[i];
    for (int i = threadIdx.x; i < 64 * H1; i += 256) {
        int r = i >> 5, k = i & 31;
        xs[r][k] = g_a2[(size_t)(row0 + r) * H1 + k];
    }
    __syncthreads();

    int col  = threadIdx.x & 63;
    int rsub = threadIdx.x >> 6;
    float bc = b2[col];
    for (int r = rsub; r < 64; r += 4) {
        float acc = 0.f;
        #pragma unroll
        for (int k = 0; k < H1; k++) acc += xs[r][k] * Ws[k * H2 + col];
        g_h2o[(size_t)(row0 + r) * H2 + col] = fmaxf(acc + bc, 0.f);
    }
}

// ---------------------------------------------------------------------------
// readout
// ---------------------------------------------------------------------------
__global__ void k_out_init(float* __restrict__ out, const float* __restrict__ bout) {
    int b = threadIdx.x;
    if (b < NBATCH) out[b] = bout[0];
}

__global__ void k_out_reduce(const float* __restrict__ Wout, float* __restrict__ out) {
    const int LEN = NODES_PB * H2;   // 640000
    int b = blockIdx.y;
    const float* h = g_h2o + (size_t)b * LEN;
    float s = 0.f;
    for (int j = blockIdx.x * blockDim.x + threadIdx.x; j < LEN; j += gridDim.x * blockDim.x)
        s += h[j] * Wout[j];
    #pragma unroll
    for (int o = 16; o > 0; o >>= 1) s += __shfl_down_sync(0xFFFFFFFFu, s, o);
    __shared__ float ws[8];
    if ((threadIdx.x & 31) == 0) ws[threadIdx.x >> 5] = s;
    __syncthreads();
    if (threadIdx.x < 8) {
        float t = ws[threadIdx.x];
        #pragma unroll
        for (int o = 4; o > 0; o >>= 1) t += __shfl_down_sync(0xFFu, t, o);
        if (threadIdx.x == 0) atomicAdd(&out[b], t);
    }
}

// ---------------------------------------------------------------------------
extern "C" void kernel_launch(void* const* d_in, const int* in_sizes, int n_in,
                              void* d_out, int out_size) {
    const float* x    = (const float*)d_in[0];
    const int*   ei   = (const int*)d_in[1];     // int32 (JAX demotes int64)
    const float* W1   = (const float*)d_in[2];
    const float* b1   = (const float*)d_in[3];
    const float* W2   = (const float*)d_in[4];
    const float* b2   = (const float*)d_in[5];
    const float* Wout = (const float*)d_in[6];
    const float* bout = (const float*)d_in[7];
    float*       out  = (float*)d_out;

    const int T = 256;
    const int nodeBlk = (N_NODES + T - 1) / T;
    const int edgeBlk = (NEDGES + T - 1) / T;
    const int warpBlk = (N_NODES * 32 + T - 1) / T;   // warp-per-node grids

    // CSR build
    k_cnt_init<<<nodeBlk, T>>>();
    k_deg_count<<<edgeBlk, T>>>(ei);
    k_scan_a<<<NBLK_SCAN, SCAN_B>>>();
    k_scan_c<<<NBLK_SCAN, SCAN_B>>>();
    k_place<<<edgeBlk, T>>>(ei);

    // layer 1: transform -> aggregate (+bias+relu)
    k_gemm1<<<N_NODES / 32, T>>>(x, W1);
    k_gather1<<<warpBlk, T>>>(b1);

    // layer 2: aggregate -> transform (+bias+relu)  [linearity commute]
    k_gather2<<<warpBlk, T>>>();
    k_gemm2<<<N_NODES / 64, T>>>(W2, b2);

    // readout
    k_out_init<<<1, 32>>>(out, bout);
    dim3 og(40, NBATCH);
    k_out_reduce<<<og, T>>>(Wout, out);
}

// round 8
// speedup vs baseline: 1.4462x; 1.3995x over previous
#include <cuda_runtime.h>
#include <cuda_bf16.h>

#define N_NODES   80000
#define NODES_PB  10000
#define NBATCH    8
#define NEDGES    2560000
#define IN_DIM    128
#define H1        32
#define H2        64

#define SCAN_B    1024
#define NBLK_SCAN ((N_NODES + SCAN_B - 1) / SCAN_B)   // 79

// ---- scratch (__device__ globals; no allocation allowed) ----
__device__ float g_dinv[N_NODES];
__device__ int   g_cnt[N_NODES];
__device__ int   g_rowstart[N_NODES + 1];
__device__ int   g_cursor[N_NODES];
__device__ int   g_bsum[NBLK_SCAN];
__device__ int2  g_edge[NEDGES];               // {src, weight-as-bits}

__device__ __align__(128) float g_h1t[N_NODES * H1];  // x@W1
__device__ __align__(128) float g_h1o[N_NODES * H1];  // relu(agg1+b1)
__device__ __align__(128) float g_a2 [N_NODES * H1];  // agg(h1o)
__device__ __align__(128) float g_h2o[N_NODES * H2];  // relu(a2@W2+b2)

// ---------------------------------------------------------------------------
// CSR build
// ---------------------------------------------------------------------------
__global__ void k_cnt_init() {
    int i = blockIdx.x * blockDim.x + threadIdx.x;
    if (i < N_NODES) g_cnt[i] = 0;
}

__global__ void k_deg_count(const int* __restrict__ ei) {
    int e = blockIdx.x * blockDim.x + threadIdx.x;
    if (e < NEDGES) atomicAdd(&g_cnt[ei[NEDGES + e]], 1);
}

__global__ void k_scan_a() {
    __shared__ int sh[SCAN_B / 32];
    int i = blockIdx.x * SCAN_B + threadIdx.x;
    int v = (i < N_NODES) ? g_cnt[i] : 0;
    #pragma unroll
    for (int o = 16; o > 0; o >>= 1) v += __shfl_down_sync(0xFFFFFFFFu, v, o);
    if ((threadIdx.x & 31) == 0) sh[threadIdx.x >> 5] = v;
    __syncthreads();
    if (threadIdx.x < SCAN_B / 32) {
        int t = sh[threadIdx.x];
        #pragma unroll
        for (int o = SCAN_B / 64; o > 0; o >>= 1) t += __shfl_down_sync(0xFFFFFFFFu, t, o);
        if (threadIdx.x == 0) g_bsum[blockIdx.x] = t;
    }
    if (blockIdx.x == 0 && threadIdx.x == 0) g_rowstart[N_NODES] = NEDGES;
}

__global__ void k_scan_c() {
    __shared__ int sh[SCAN_B];
    __shared__ int s_off;
    int tid = threadIdx.x;

    if (tid < 32) {
        int v = 0;
        for (int b = tid; b < blockIdx.x; b += 32) v += g_bsum[b];
        #pragma unroll
        for (int o = 16; o > 0; o >>= 1) v += __shfl_down_sync(0xFFFFFFFFu, v, o);
        if (tid == 0) s_off = v;
    }

    int i = blockIdx.x * SCAN_B + tid;
    int v = (i < N_NODES) ? g_cnt[i] : 0;
    sh[tid] = v;
    __syncthreads();
    #pragma unroll
    for (int off = 1; off < SCAN_B; off <<= 1) {
        int t = (tid >= off) ? sh[tid - off] : 0;
        __syncthreads();
        sh[tid] += t;
        __syncthreads();
    }
    if (i < N_NODES) {
        int excl = sh[tid] - v + s_off;
        g_rowstart[i] = excl;
        g_cursor[i]   = excl;
        g_dinv[i]     = rsqrtf((float)(v + 1));   // +1 self-loop
    }
}

__global__ void k_place(const int* __restrict__ ei) {
    int e = blockIdx.x * blockDim.x + threadIdx.x;
    if (e >= NEDGES) return;
    int s = ei[e];
    int d = ei[NEDGES + e];
    int slot = atomicAdd(&g_cursor[d], 1);
    g_edge[slot] = make_int2(s, __float_as_int(g_dinv[s] * g_dinv[d]));
}

// ---------------------------------------------------------------------------
// GEMM1: g_h1t = x @ W1   (80000x128 @ 128x32)
// 256 thr, tile 128 rows x 32 cols, micro-tile TM=4 x TN=4, k chunked by 32.
// ---------------------------------------------------------------------------
__global__ void k_gemm1(const float* __restrict__ x, const float* __restrict__ W1) {
    __shared__ float Ws[IN_DIM][H1];          // [k][col] 16KB
    __shared__ float xsT[32][132];            // [k][row] transposed, padded
    int row0 = blockIdx.x * 128;
    int tx = threadIdx.x & 7;                 // cols tx*4 .. +3
    int ty = threadIdx.x >> 3;                // rows ty*4 .. +3

    for (int i = threadIdx.x; i < IN_DIM * H1; i += 256)
        Ws[i >> 5][i & 31] = W1[i];

    float acc[4][4] = {};
    for (int k0 = 0; k0 < IN_DIM; k0 += 32) {
        __syncthreads();
        for (int i = threadIdx.x; i < 128 * 32; i += 256) {
            int r = i >> 5, k = i & 31;
            xsT[k][r] = x[(size_t)(row0 + r) * IN_DIM + k0 + k];
        }
        __syncthreads();
        #pragma unroll
        for (int k = 0; k < 32; k++) {
            float4 xv = *(const float4*)&xsT[k][ty * 4];
            float4 wv = *(const float4*)&Ws[k0 + k][tx * 4];
            acc[0][0] += xv.x * wv.x; acc[0][1] += xv.x * wv.y; acc[0][2] += xv.x * wv.z; acc[0][3] += xv.x * wv.w;
            acc[1][0] += xv.y * wv.x; acc[1][1] += xv.y * wv.y; acc[1][2] += xv.y * wv.z; acc[1][3] += xv.y * wv.w;
            acc[2][0] += xv.z * wv.x; acc[2][1] += xv.z * wv.y; acc[2][2] += xv.z * wv.z; acc[2][3] += xv.z * wv.w;
            acc[3][0] += xv.w * wv.x; acc[3][1] += xv.w * wv.y; acc[3][2] += xv.w * wv.z; acc[3][3] += xv.w * wv.w;
        }
    }
    #pragma unroll
    for (int i = 0; i < 4; i++) {
        float4 o = make_float4(acc[i][0], acc[i][1], acc[i][2], acc[i][3]);
        *(float4*)&g_h1t[(size_t)(row0 + ty * 4 + i) * H1 + tx * 4] = o;
    }
}

// ---------------------------------------------------------------------------
// gathers: warp per node, 4 edges in flight (8 lanes x float4 each), with
// edge-record prefetch and shfl-xor cross-subgroup reduction.
// ---------------------------------------------------------------------------
__device__ __forceinline__ void gather_node(const float* __restrict__ hsrc,
                                            float* __restrict__ hdst,
                                            const float* __restrict__ bias,  // nullptr -> no bias/relu
                                            int node, int lane) {
    int cg = lane >> 3;        // edge subgroup 0..3
    int cl = lane & 7;         // float4 column group 0..7
    int beg = g_rowstart[node], end = g_rowstart[node + 1];
    const float4* h4 = (const float4*)hsrc;

    float4 acc = make_float4(0.f, 0.f, 0.f, 0.f);
    if (cg == 0) {
        float dn = g_dinv[node];
        float4 sv = h4[(size_t)node * 8 + cl];
        float w = dn * dn;
        acc = make_float4(sv.x * w, sv.y * w, sv.z * w, sv.w * w);
    }

    int e = beg + cg;
    if (e < end) {
        int2 ev = g_edge[e];
        while (true) {
            int en = e + 4;
            bool more = en < end;
            int2 evn = more ? g_edge[en] : make_int2(0, 0);
            float4 v = h4[(size_t)ev.x * 8 + cl];
            float w = __int_as_float(ev.y);
            acc.x += v.x * w; acc.y += v.y * w; acc.z += v.z * w; acc.w += v.w * w;
            if (!more) break;
            ev = evn; e = en;
        }
    }

    __syncwarp();
    #pragma unroll
    for (int o = 8; o <= 16; o <<= 1) {
        acc.x += __shfl_xor_sync(0xFFFFFFFFu, acc.x, o);
        acc.y += __shfl_xor_sync(0xFFFFFFFFu, acc.y, o);
        acc.z += __shfl_xor_sync(0xFFFFFFFFu, acc.z, o);
        acc.w += __shfl_xor_sync(0xFFFFFFFFu, acc.w, o);
    }
    if (cg == 0) {
        if (bias) {
            float4 bv = *(const float4*)&bias[cl * 4];
            acc.x = fmaxf(acc.x + bv.x, 0.f);
            acc.y = fmaxf(acc.y + bv.y, 0.f);
            acc.z = fmaxf(acc.z + bv.z, 0.f);
            acc.w = fmaxf(acc.w + bv.w, 0.f);
        }
        *(float4*)&hdst[(size_t)node * H1 + cl * 4] = acc;
    }
}

__global__ void k_gather1(const float* __restrict__ b1) {
    int node = (blockIdx.x * blockDim.x + threadIdx.x) >> 5;
    if (node >= N_NODES) return;
    gather_node(g_h1t, g_h1o, b1, node, threadIdx.x & 31);
}

__global__ void k_gather2() {
    int node = (blockIdx.x * blockDim.x + threadIdx.x) >> 5;
    if (node >= N_NODES) return;
    gather_node(g_h1o, g_a2, nullptr, node, threadIdx.x & 31);
}

// ---------------------------------------------------------------------------
// GEMM2: g_h2o = relu(a2 @ W2 + b2)  (80000x32 @ 32x64)
// 256 thr, tile 128 rows x 64 cols, micro-tile TM=8 x TN=4, K=32.
// ---------------------------------------------------------------------------
__global__ void k_gemm2(const float* __restrict__ W2, const float* __restrict__ b2) {
    __shared__ float Ws2[H1][H2];             // 8KB
    __shared__ float asT[H1][132];            // [k][row] 16.9KB
    int row0 = blockIdx.x * 128;
    int tx = threadIdx.x & 15;                // cols tx*4 .. +3
    int ty = threadIdx.x >> 4;                // rows ty*8 .. +7

    for (int i = threadIdx.x; i < H1 * H2; i += 256)
        Ws2[i >> 6][i & 63] = W2[i];
    for (int i = threadIdx.x; i < 128 * 32; i += 256) {
        int r = i >> 5, k = i & 31;
        asT[k][r] = g_a2[(size_t)(row0 + r) * H1 + k];
    }
    __syncthreads();

    float acc[8][4] = {};
    #pragma unroll
    for (int k = 0; k < H1; k++) {
        float4 x0 = *(const float4*)&asT[k][ty * 8];
        float4 x1 = *(const float4*)&asT[k][ty * 8 + 4];
        float4 wv = *(const float4*)&Ws2[k][tx * 4];
        float xr[8] = {x0.x, x0.y, x0.z, x0.w, x1.x, x1.y, x1.z, x1.w};
        #pragma unroll
        for (int i = 0; i < 8; i++) {
            acc[i][0] += xr[i] * wv.x;
            acc[i][1] += xr[i] * wv.y;
            acc[i][2] += xr[i] * wv.z;
            acc[i][3] += xr[i] * wv.w;
        }
    }
    float4 bv = *(const float4*)&b2[tx * 4];
    #pragma unroll
    for (int i = 0; i < 8; i++) {
        float4 o;
        o.x = fmaxf(acc[i][0] + bv.x, 0.f);
        o.y = fmaxf(acc[i][1] + bv.y, 0.f);
        o.z = fmaxf(acc[i][2] + bv.z, 0.f);
        o.w = fmaxf(acc[i][3] + bv.w, 0.f);
        *(float4*)&g_h2o[(size_t)(row0 + ty * 8 + i) * H2 + tx * 4] = o;
    }
}

// ---------------------------------------------------------------------------
// readout
// ---------------------------------------------------------------------------
__global__ void k_out_init(float* __restrict__ out, const float* __restrict__ bout) {
    int b = threadIdx.x;
    if (b < NBATCH) out[b] = bout[0];
}

__global__ void k_out_reduce(const float* __restrict__ Wout, float* __restrict__ out) {
    const int LEN = NODES_PB * H2;   // 640000
    int b = blockIdx.y;
    const float4* h = (const float4*)(g_h2o + (size_t)b * LEN);
    const float4* w = (const float4*)Wout;
    float s = 0.f;
    for (int j = blockIdx.x * blockDim.x + threadIdx.x; j < LEN / 4; j += gridDim.x * blockDim.x) {
        float4 hv = h[j], wv = w[j];
        s += hv.x * wv.x + hv.y * wv.y + hv.z * wv.z + hv.w * wv.w;
    }
    #pragma unroll
    for (int o = 16; o > 0; o >>= 1) s += __shfl_down_sync(0xFFFFFFFFu, s, o);
    __shared__ float ws[8];
    if ((threadIdx.x & 31) == 0) ws[threadIdx.x >> 5] = s;
    __syncthreads();
    if (threadIdx.x < 8) {
        float t = ws[threadIdx.x];
        #pragma unroll
        for (int o = 4; o > 0; o >>= 1) t += __shfl_down_sync(0xFFu, t, o);
        if (threadIdx.x == 0) atomicAdd(&out[b], t);
    }
}

// ---------------------------------------------------------------------------
extern "C" void kernel_launch(void* const* d_in, const int* in_sizes, int n_in,
                              void* d_out, int out_size) {
    const float* x    = (const float*)d_in[0];
    const int*   ei   = (const int*)d_in[1];     // int32 (JAX demotes int64)
    const float* W1   = (const float*)d_in[2];
    const float* b1   = (const float*)d_in[3];
    const float* W2   = (const float*)d_in[4];
    const float* b2   = (const float*)d_in[5];
    const float* Wout = (const float*)d_in[6];
    const float* bout = (const float*)d_in[7];
    float*       out  = (float*)d_out;

    const int T = 256;
    const int nodeBlk = (N_NODES + T - 1) / T;
    const int edgeBlk = (NEDGES + T - 1) / T;
    const int warpBlk = (N_NODES * 32 + T - 1) / T;

    // CSR build
    k_cnt_init<<<nodeBlk, T>>>();
    k_deg_count<<<edgeBlk, T>>>(ei);
    k_scan_a<<<NBLK_SCAN, SCAN_B>>>();
    k_scan_c<<<NBLK_SCAN, SCAN_B>>>();
    k_place<<<edgeBlk, T>>>(ei);

    // layer 1: transform -> aggregate (+bias+relu)
    k_gemm1<<<N_NODES / 128, T>>>(x, W1);
    k_gather1<<<warpBlk, T>>>(b1);

    // layer 2: aggregate -> transform (+bias+relu)
    k_gather2<<<warpBlk, T>>>();
    k_gemm2<<<N_NODES / 128, T>>>(W2, b2);

    // readout
    k_out_init<<<1, 32>>>(out, bout);
    dim3 og(40, NBATCH);
    k_out_reduce<<<og, T>>>(Wout, out);
}